// round 8
// baseline (speedup 1.0000x reference)
#include <cuda_runtime.h>
#include <math.h>

#define HS 1080
#define WS 1920
#define OUTW 3840
#define MAXN 256
#define MAXM 256
#define MAXK (2*MAXN + MAXM)
#define SUBS 8
#define DETS_PER_PASS 128   // 1024 threads / 8 subs

// Rect table scratch (allocation-free: __device__ globals)
__device__ int4  g_rbox[MAXK];   // subsampled int boxes (x1,y1,x2,y2)
__device__ float g_rval[MAXK];   // paint value (<=0 -> culled)

// Single-block fused setup: IoU matching + rect table + matched-masking.
__global__ void __launch_bounds__(1024) setup_kernel(
    const float4* __restrict__ boxes, const float* __restrict__ scores,
    const float* __restrict__ flags,
    const float4* __restrict__ boxes_prev, const float* __restrict__ scores_prev,
    const float* __restrict__ flags_prev,
    const int* __restrict__ ids, const int* __restrict__ ids_prev,
    int N, int M)
{
    __shared__ float4 s_pb[MAXM];                 // floored prev boxes
    __shared__ float  s_parea[MAXM], s_ps[MAXM], s_pf[MAXM];
    __shared__ int    s_pid[MAXM];
    __shared__ int    s_matched[MAXM];
    __shared__ float  p_best[1024], p_ioum[1024];
    __shared__ int    p_bidx[1024], p_midx[1024];

    int t = threadIdx.x;

    // Load prev-det data into shared (subsampled, floored boxes kept as floats)
    for (int j = t; j < M; j += blockDim.x) {
        float4 b = boxes_prev[j];
        float x1 = floorf(b.x * 0.5f), y1 = floorf(b.y * 0.5f);
        float x2 = floorf(b.z * 0.5f), y2 = floorf(b.w * 0.5f);
        s_pb[j] = make_float4(x1, y1, x2, y2);
        s_parea[j] = (x2 - x1) * (y2 - y1);
        s_ps[j] = scores_prev[j];
        s_pf[j] = flags_prev[j];
        s_pid[j] = ids_prev[j];
        s_matched[j] = 0;
    }
    __syncthreads();

    int sub = t & 7;

    for (int det0 = 0; det0 < N; det0 += DETS_PER_PASS) {
        int det = det0 + (t >> 3);   // 8 threads per det

        float bx1 = 0.f, by1 = 0.f, bx2 = 0.f, by2 = 0.f;

        if (det < N) {
            float4 b = boxes[det];
            bx1 = floorf(b.x * 0.5f); by1 = floorf(b.y * 0.5f);
            bx2 = floorf(b.z * 0.5f); by2 = floorf(b.w * 0.5f);
            float area = (bx2 - bx1) * (by2 - by1);
            int myid = ids[det];

            int chunk = (M + SUBS - 1) / SUBS;
            int j0 = sub * chunk;
            int j1 = min(M, j0 + chunk);

            float best = -3.0f, ioum = 0.0f, iou0 = 0.0f;
            int bidx = 0, midx = -1;
            for (int j = j0; j < j1; j++) {
                float4 p = s_pb[j];
                float ix1 = fmaxf(bx1, p.x), iy1 = fmaxf(by1, p.y);
                float ix2 = fminf(bx2, p.z), iy2 = fminf(by2, p.w);
                float inter = fmaxf(ix2 - ix1, 0.0f) * fmaxf(iy2 - iy1, 0.0f);
                float iou = inter / (area + s_parea[j] - inter);  // exact IEEE div
                bool ism = (s_pid[j] == myid);
                if (ism) { midx = j; ioum = iou; }
                float v = ism ? -1.0f : iou;
                if (v > best) { best = v; bidx = j; }  // strict > keeps first argmax
                if (j == 0) iou0 = iou;                // only sub 0 ever hits j==0
            }
            // reference: no id match -> midx=0, iou_m = iou[i][0] (sub 0's iou0)
            if (midx < 0) ioum = iou0;

            p_best[t] = best; p_bidx[t] = bidx;
            p_ioum[t] = ioum; p_midx[t] = midx;
        }
        __syncthreads();

        if (det < N && sub == 0) {
            float best = -3.0f, ioum = p_ioum[t];
            int bidx = 0, midx = 0;
            bool hasm = false;
            #pragma unroll
            for (int s = 0; s < SUBS; s++) {
                float b = p_best[t + s];
                if (b > best) { best = b; bidx = p_bidx[t + s]; }  // chunks ascend
                if (!hasm && p_midx[t + s] >= 0) {
                    hasm = true; midx = p_midx[t + s]; ioum = p_ioum[t + s];
                }
            }

            float fl = flags[det];
            float sc = scores[det];
            bool  flag1    = (fl == 1.0f);
            bool  has_best = (best > 0.0f);
            float best_iou = fmaxf(best, 0.0f);
            float ig1 = 1.0f - best_iou;
            float ig0 = 1.0f - ioum;

            // rect[det]: current box
            float val_cur = flag1 ? (ig1 * sc) : (ig0 * sc * (1.0f - fl));
            g_rbox[det] = make_int4((int)bx1, (int)by1, (int)bx2, (int)by2);
            g_rval[det] = val_cur;

            // rect[N+det]: associated prev box
            float sp1 = s_ps[bidx], fp1 = s_pf[bidx];
            float v1 = ig1 * ((fp1 == 1.0f) ? sp1 : sp1 * (1.0f - fp1));
            float sp0 = s_ps[midx], fp0 = s_pf[midx];
            float v0 = ig0 * ((fp0 == 1.0f) ? sp0 : sp0 * (1.0f - fl)); // (1-cur flag)
            int   pj   = flag1 ? bidx : midx;
            float pv   = flag1 ? v1 : v0;
            bool  pact = flag1 ? has_best : hasm;
            float4 pb = s_pb[pj];
            g_rbox[N + det] = make_int4((int)pb.x, (int)pb.y, (int)pb.z, (int)pb.w);
            g_rval[N + det] = pact ? pv : 0.0f;
            if (pact) s_matched[pj] = 1;   // non-atomic: all writers store 1
        }
        __syncthreads();
    }

    // rect[2N+j]: leftover (unmatched) prev dets, masked in-shared
    for (int j = t; j < M; j += blockDim.x) {
        float spv = s_ps[j], fpv = s_pf[j];
        float vu = (fpv == 1.0f) ? spv : spv * (1.0f - fpv);
        float4 pb = s_pb[j];
        g_rbox[2 * N + j] = make_int4((int)pb.x, (int)pb.y, (int)pb.z, (int)pb.w);
        g_rval[2 * N + j] = s_matched[j] ? 0.0f : vu;
    }

#if __CUDA_ARCH__ >= 900
    cudaTriggerProgrammaticLaunchCompletion();
#endif
}

// Tile: 64 (x) x 16 (y) sub-pixels per block, 256 threads, each owns a 2x2
// sub-pixel patch -> writes a 4x4 full-res patch via 4 float4 stores.
// Launched with programmatic stream serialization: prologue overlaps setup.
__global__ void __launch_bounds__(256) paint_kernel(float* __restrict__ out, int K)
{
    __shared__ int4  c_box[MAXK];
    __shared__ float c_val[MAXK];
    __shared__ int   scount;

    int t = threadIdx.x;
    if (t == 0) scount = 0;

    int tx0 = blockIdx.x * 64;
    int ty0 = blockIdx.y * 16;
    int sx = tx0 + ((t & 31) << 1);
    int sy = ty0 + ((t >> 5) << 1);

#if __CUDA_ARCH__ >= 900
    cudaGridDependencySynchronize();   // wait for setup's rect table
#endif
    __syncthreads();

    // Cull rects into shared compact list
    for (int r = t; r < K; r += blockDim.x) {
        float v = g_rval[r];
        int4 b = g_rbox[r];
        if (v > 0.0f && b.x < tx0 + 64 && b.z > tx0 && b.y < ty0 + 16 && b.w > ty0) {
            int idx = atomicAdd(&scount, 1);
            c_box[idx] = b;
            c_val[idx] = v;
        }
    }
    __syncthreads();

    float v00 = 0.0f, v01 = 0.0f, v10 = 0.0f, v11 = 0.0f;
    int n = scount;
    for (int r = 0; r < n; r++) {
        int4 b = c_box[r];
        float v = c_val[r];
        bool inx0 = (sx     >= b.x) & (sx     < b.z);
        bool inx1 = (sx + 1 >= b.x) & (sx + 1 < b.z);
        bool iny0 = (sy     >= b.y) & (sy     < b.w);
        bool iny1 = (sy + 1 >= b.y) & (sy + 1 < b.w);
        if (inx0 & iny0) v00 = fmaxf(v00, v);
        if (inx1 & iny0) v01 = fmaxf(v01, v);
        if (inx0 & iny1) v10 = fmaxf(v10, v);
        if (inx1 & iny1) v11 = fmaxf(v11, v);
    }

    if (sy < HS) {  // last block row is partial in y (1080 = 67*16 + 8)
        int gx = sx << 1;
        int gy = sy << 1;
        float4 a = make_float4(v00, v00, v01, v01);
        float4 b = make_float4(v10, v10, v11, v11);
        float4* p0 = (float4*)(out + (size_t)(gy    ) * OUTW + gx);
        float4* p1 = (float4*)(out + (size_t)(gy + 1) * OUTW + gx);
        float4* p2 = (float4*)(out + (size_t)(gy + 2) * OUTW + gx);
        float4* p3 = (float4*)(out + (size_t)(gy + 3) * OUTW + gx);
        *p0 = a; *p1 = a;
        *p2 = b; *p3 = b;
    }
}

extern "C" void kernel_launch(void* const* d_in, const int* in_sizes, int n_in,
                              void* d_out, int out_size)
{
    // metadata order: inputs, boxes, scores, flags, boxes_prev, scores_prev,
    //                 flags_prev, ids, ids_prev
    const float4* boxes      = (const float4*)d_in[1];
    const float*  scores     = (const float*)d_in[2];
    const float*  flags      = (const float*)d_in[3];
    const float4* boxes_prev = (const float4*)d_in[4];
    const float*  scores_prev= (const float*)d_in[5];
    const float*  flags_prev = (const float*)d_in[6];
    const int*    ids        = (const int*)d_in[7];
    const int*    ids_prev   = (const int*)d_in[8];

    int N = in_sizes[2];   // scores element count
    int M = in_sizes[5];   // scores_prev element count

    setup_kernel<<<1, 1024>>>(boxes, scores, flags, boxes_prev, scores_prev,
                              flags_prev, ids, ids_prev, N, M);

    // Paint with PDL: starts during setup, syncs before reading rect table.
    cudaLaunchConfig_t cfg = {};
    cfg.gridDim  = dim3(WS / 64, (HS + 15) / 16);   // 30 x 68
    cfg.blockDim = dim3(256);
    cfg.dynamicSmemBytes = 0;
    cfg.stream = 0;
    cudaLaunchAttribute attrs[1];
    attrs[0].id = cudaLaunchAttributeProgrammaticStreamSerialization;
    attrs[0].val.programmaticStreamSerializationAllowed = 1;
    cfg.attrs = attrs;
    cfg.numAttrs = 1;
    cudaLaunchKernelEx(&cfg, paint_kernel, (float*)d_out, 2 * N + M);
}